// round 3
// baseline (speedup 1.0000x reference)
#include <cuda_runtime.h>
#include <math.h>

#define B   8
#define C   64
#define T   4096
#define KNN 9

// Scratch (allocation-free: __device__ globals)
__device__ float g_qT[B * T * C];          // normalized q, [b][t][c]
__device__ float g_kT[B * T * C];          // normalized k, [b][t][c]
__device__ float g_vT[B * T * C];          // v, [b][t][c]
__device__ float g_wP[KNN * C * C];        // conv_w permuted: [kk][cc][o]
__device__ int   g_idx[B * T * KNN];       // top-9 neighbor indices per (b,i)

// ---------------------------------------------------------------------------
// Kernel 0: permute conv_w[o][cc*9+kk] -> wP[kk][cc][o]
// ---------------------------------------------------------------------------
__global__ void permute_w_kernel(const float* __restrict__ conv_w) {
    int s = blockIdx.x * 256 + threadIdx.x;
    if (s < KNN * C * C) {
        int o  = s & 63;
        int cc = (s >> 6) & 63;
        int kk = s >> 12;
        g_wP[s] = conv_w[o * (C * KNN) + cc * KNN + kk];
    }
}

// ---------------------------------------------------------------------------
// Kernel 1: q/k/v projections + L2 normalize (k,q), write transposed [b][t][c]
// Numerics chosen to reproduce XLA/cuBLAS fp32:
//   - projection: sequential fused FMA over c = 0..63 (in order)
//   - sum-of-squares: sequential separate mul + add (no contraction)
//   - norm: fmax(sqrtf(ss), 1e-12), then IEEE division (not recip-mul)
// ---------------------------------------------------------------------------
__global__ __launch_bounds__(128) void proj_kernel(
    const float* __restrict__ x,
    const float* __restrict__ Wq,
    const float* __restrict__ Wk,
    const float* __restrict__ Wv)
{
    __shared__ float Xs[C][128];   // 32 KB
    __shared__ float Ws[C][C];     // 16 KB, [c][d] (transposed for float4 d-reads)

    const int b   = blockIdx.y;
    const int t0  = blockIdx.x * 128;
    const int tid = threadIdx.x;

    const float* xb = x + (size_t)b * C * T;
    for (int c = 0; c < C; c++)
        Xs[c][tid] = xb[c * T + t0 + tid];

    for (int m = 0; m < 3; m++) {
        const float* W = (m == 0) ? Wq : ((m == 1) ? Wk : Wv);
        float* dstbase = (m == 0) ? g_qT : ((m == 1) ? g_kT : g_vT);

        __syncthreads();   // protect Ws from previous iteration's readers
        for (int s = tid; s < C * C; s += 128) {
            int c = s >> 6, d = s & 63;
            Ws[c][d] = W[d * C + c];
        }
        __syncthreads();

        float acc[C];
        #pragma unroll
        for (int d = 0; d < C; d++) acc[d] = 0.f;

        // acc[d] accumulated sequentially over c (matches gemm k-loop order)
        for (int c = 0; c < C; c++) {
            float xv = Xs[c][tid];
            const float4* wr = (const float4*)Ws[c];
            #pragma unroll
            for (int d4 = 0; d4 < 16; d4++) {
                float4 w = wr[d4];
                acc[4*d4+0] = __fmaf_rn(w.x, xv, acc[4*d4+0]);
                acc[4*d4+1] = __fmaf_rn(w.y, xv, acc[4*d4+1]);
                acc[4*d4+2] = __fmaf_rn(w.z, xv, acc[4*d4+2]);
                acc[4*d4+3] = __fmaf_rn(w.w, xv, acc[4*d4+3]);
            }
        }

        if (m < 2) {  // L2 normalize over channel dim (q and k)
            float ss = 0.f;
            #pragma unroll
            for (int d = 0; d < C; d++)
                ss = __fadd_rn(ss, __fmul_rn(acc[d], acc[d]));   // no fma contraction
            float n = fmaxf(sqrtf(ss), 1e-12f);
            #pragma unroll
            for (int d = 0; d < C; d++)
                acc[d] = __fdiv_rn(acc[d], n);                   // IEEE division
        }

        float4* dst = (float4*)(dstbase + ((size_t)b * T + t0 + tid) * C);
        #pragma unroll
        for (int d4 = 0; d4 < 16; d4++)
            dst[d4] = make_float4(acc[4*d4+0], acc[4*d4+1], acc[4*d4+2], acc[4*d4+3]);
    }
}

// ---------------------------------------------------------------------------
// Kernel 2: fused sim = k_norm . q_norm (clamped at 0) + streaming top-9.
// Dot product: sequential single-accumulator FMA chain over c = 0..63
// (bitwise-matching the reference gemm). 4 candidates unrolled for ILP.
// ---------------------------------------------------------------------------
#define CSWAP(va, ja, vb, jb)                                     \
    do { if ((vb) > (va)) {                                       \
        float _tv = (va); (va) = (vb); (vb) = _tv;                \
        int   _tj = (ja); (ja) = (jb); (jb) = _tj; } } while (0)

#define TOPK_INSERT(s, j)                                         \
    do { if ((s) > v8) {                                          \
        v8 = (s); j8 = (j);                                       \
        CSWAP(v7, j7, v8, j8);                                    \
        CSWAP(v6, j6, v7, j7);                                    \
        CSWAP(v5, j5, v6, j6);                                    \
        CSWAP(v4, j4, v5, j5);                                    \
        CSWAP(v3, j3, v4, j4);                                    \
        CSWAP(v2, j2, v3, j3);                                    \
        CSWAP(v1, j1, v2, j2);                                    \
        CSWAP(v0, j0, v1, j1); } } while (0)

__global__ __launch_bounds__(256) void sim_topk_kernel()
{
    __shared__ float Qs[128 * C];   // 32 KB, [jj][c]

    const int b   = blockIdx.y;
    const int tid = threadIdx.x;
    const int i   = blockIdx.x * 256 + tid;

    float kr[C];
    {
        const float4* krow = (const float4*)(g_kT + ((size_t)b * T + i) * C);
        #pragma unroll
        for (int c4 = 0; c4 < 16; c4++) {
            float4 k4 = krow[c4];
            kr[4*c4+0] = k4.x; kr[4*c4+1] = k4.y;
            kr[4*c4+2] = k4.z; kr[4*c4+3] = k4.w;
        }
    }

    // sorted descending top-9 (values clamped >= 0, so -1 sentinels always lose)
    float v0=-1.f,v1=-1.f,v2=-1.f,v3=-1.f,v4=-1.f,v5=-1.f,v6=-1.f,v7=-1.f,v8=-1.f;
    int   j0=0,j1=0,j2=0,j3=0,j4=0,j5=0,j6=0,j7=0,j8=0;

    for (int jt = 0; jt < T; jt += 128) {
        __syncthreads();
        {
            const float4* src = (const float4*)(g_qT + ((size_t)b * T + jt) * C);
            float4* qd = (float4*)Qs;
            #pragma unroll
            for (int r = 0; r < 8; r++)
                qd[r * 256 + tid] = src[r * 256 + tid];
        }
        __syncthreads();

        for (int jj = 0; jj < 128; jj += 4) {
            const float4* qa = (const float4*)(Qs + (jj + 0) * C);
            const float4* qb = (const float4*)(Qs + (jj + 1) * C);
            const float4* qc = (const float4*)(Qs + (jj + 2) * C);
            const float4* qd = (const float4*)(Qs + (jj + 3) * C);
            float sa = 0.f, sb = 0.f, sc = 0.f, sd = 0.f;
            #pragma unroll
            for (int c4 = 0; c4 < 16; c4++) {
                float4 a4 = qa[c4], b4 = qb[c4], c4v = qc[c4], d4 = qd[c4];
                // each s* is a strictly sequential chain over c (order c=0..63);
                // the four chains interleave for ILP
                sa = __fmaf_rn(kr[4*c4+0], a4.x, sa);
                sb = __fmaf_rn(kr[4*c4+0], b4.x, sb);
                sc = __fmaf_rn(kr[4*c4+0], c4v.x, sc);
                sd = __fmaf_rn(kr[4*c4+0], d4.x, sd);
                sa = __fmaf_rn(kr[4*c4+1], a4.y, sa);
                sb = __fmaf_rn(kr[4*c4+1], b4.y, sb);
                sc = __fmaf_rn(kr[4*c4+1], c4v.y, sc);
                sd = __fmaf_rn(kr[4*c4+1], d4.y, sd);
                sa = __fmaf_rn(kr[4*c4+2], a4.z, sa);
                sb = __fmaf_rn(kr[4*c4+2], b4.z, sb);
                sc = __fmaf_rn(kr[4*c4+2], c4v.z, sc);
                sd = __fmaf_rn(kr[4*c4+2], d4.z, sd);
                sa = __fmaf_rn(kr[4*c4+3], a4.w, sa);
                sb = __fmaf_rn(kr[4*c4+3], b4.w, sb);
                sc = __fmaf_rn(kr[4*c4+3], c4v.w, sc);
                sd = __fmaf_rn(kr[4*c4+3], d4.w, sd);
            }
            sa = fmaxf(sa, 0.f);
            sb = fmaxf(sb, 0.f);
            sc = fmaxf(sc, 0.f);
            sd = fmaxf(sd, 0.f);
            // inserts in increasing-j order preserve jax top_k tie-breaking
            TOPK_INSERT(sa, jt + jj + 0);
            TOPK_INSERT(sb, jt + jj + 1);
            TOPK_INSERT(sc, jt + jj + 2);
            TOPK_INSERT(sd, jt + jj + 3);
        }
    }

    int* op = g_idx + ((size_t)b * T + i) * KNN;
    op[0]=j0; op[1]=j1; op[2]=j2; op[3]=j3; op[4]=j4;
    op[5]=j5; op[6]=j6; op[7]=j7; op[8]=j8;
}

// ---------------------------------------------------------------------------
// Kernel 3: gather v at top-9 neighbors + 1x1 conv (576 -> 64) + bias.
// One thread per output column i; 64 accumulators; wP chunk staged per kk.
// ---------------------------------------------------------------------------
__global__ __launch_bounds__(128) void gather_conv_kernel(
    const float* __restrict__ conv_b,
    float* __restrict__ out)
{
    __shared__ float Ws[C * C];   // 16 KB, [cc][o] for current kk

    const int b   = blockIdx.y;
    const int tid = threadIdx.x;
    const int i   = blockIdx.x * 128 + tid;

    float acc[C];
    #pragma unroll
    for (int o = 0; o < C; o++) acc[o] = 0.f;

    const int base = (b * T + i) * KNN;

    for (int kk = 0; kk < KNN; kk++) {
        __syncthreads();
        {
            const float4* wsrc = (const float4*)(g_wP + kk * C * C);
            float4* wdst = (float4*)Ws;
            #pragma unroll
            for (int r = 0; r < 8; r++)
                wdst[r * 128 + tid] = wsrc[r * 128 + tid];
        }
        __syncthreads();

        int j = g_idx[base + kk];
        const float4* vrow = (const float4*)(g_vT + ((size_t)b * T + j) * C);

        #pragma unroll
        for (int c4 = 0; c4 < 16; c4++) {
            float4 xv = vrow[c4];
            float xs[4] = {xv.x, xv.y, xv.z, xv.w};
            #pragma unroll
            for (int e = 0; e < 4; e++) {
                float xe = xs[e];
                const float4* wr = (const float4*)(Ws + (c4 * 4 + e) * C);
                #pragma unroll
                for (int o4 = 0; o4 < 16; o4++) {
                    float4 w = wr[o4];
                    acc[4*o4+0] = fmaf(xe, w.x, acc[4*o4+0]);
                    acc[4*o4+1] = fmaf(xe, w.y, acc[4*o4+1]);
                    acc[4*o4+2] = fmaf(xe, w.z, acc[4*o4+2]);
                    acc[4*o4+3] = fmaf(xe, w.w, acc[4*o4+3]);
                }
            }
        }
    }

    // out[b][o][i] = acc[o] + bias[o]   (coalesced over i within a warp)
    #pragma unroll
    for (int o = 0; o < C; o++)
        out[((size_t)(b * C + o)) * T + i] = acc[o] + __ldg(&conv_b[o]);
}

// ---------------------------------------------------------------------------
extern "C" void kernel_launch(void* const* d_in, const int* in_sizes, int n_in,
                              void* d_out, int out_size)
{
    const float* x      = (const float*)d_in[0];
    const float* Wq     = (const float*)d_in[1];
    const float* Wk     = (const float*)d_in[2];
    const float* Wv     = (const float*)d_in[3];
    const float* conv_w = (const float*)d_in[4];
    const float* conv_b = (const float*)d_in[5];
    float* out          = (float*)d_out;

    permute_w_kernel<<<(KNN * C * C + 255) / 256, 256>>>(conv_w);
    proj_kernel<<<dim3(T / 128, B), 128>>>(x, Wq, Wk, Wv);
    sim_topk_kernel<<<dim3(T / 256, B), 256>>>();
    gather_conv_kernel<<<dim3(T / 128, B), 128>>>(conv_b, out);
}